// round 16
// baseline (speedup 1.0000x reference)
#include <cuda_runtime.h>
#include <cuda_fp16.h>
#include <math.h>
#include <stdint.h>

#define NTH 1024
#define BT 16
#define HD 512
#define AST 520   // activation row stride in elems (1040B = 65*16B -> ldmatrix-aligned, conflict-free)

typedef unsigned long long ull;

// Fragment-packed fp16 weights (hi part only): uint2 per (layer, warp16, kstep, ntile4, lane)
__device__ __align__(16) uint2 g_wt[2 * 16 * 32 * 4 * 32];

struct Smem {
    __half Ah[BT * AST];   // activations hi: [row][k]
    __half Al[BT * AST];   // lo
    float W0s[16 * 512];   // W0 staged
    float W3s[512 * 3];    // W3 cols 0..2 staged
    float b0s[512], b1s[512], b2s[512];
    float in[16 * BT];     // L0 input col-major [k][row]
    float x[BT][12];
    float fn[BT][3];
    float Im[9], Iinv[9], b3s[3];
};

__device__ __forceinline__ float leaky(float v) { return v >= 0.f ? v : 0.01f * v; }
__device__ __forceinline__ ull fma2(ull a, ull b, ull c) {
    ull d;
    asm("fma.rn.f32x2 %0, %1, %2, %3;" : "=l"(d) : "l"(a), "l"(b), "l"(c));
    return d;
}
__device__ __forceinline__ ull pack2(float x) {
    ull r;
    asm("mov.b64 %0, {%1, %1};" : "=l"(r) : "f"(x));
    return r;
}
__device__ __forceinline__ float2 unpack2(ull v) {
    float2 f;
    asm("mov.b64 {%0, %1}, %2;" : "=f"(f.x), "=f"(f.y) : "l"(v));
    return f;
}
__device__ __forceinline__ uint32_t s2u(const void* p) {
    uint32_t a;
    asm("{ .reg .u64 t; cvta.to.shared.u64 t, %1; cvt.u32.u64 %0, t; }" : "=r"(a) : "l"(p));
    return a;
}

// mma.m16n8k16 row.col fp16 -> f32 accum
__device__ __forceinline__ void mma16816(float d[4], unsigned a0, unsigned a1, unsigned a2,
                                         unsigned a3, unsigned b0, unsigned b1) {
    asm volatile(
        "mma.sync.aligned.m16n8k16.row.col.f32.f16.f16.f32 "
        "{%0,%1,%2,%3}, {%4,%5,%6,%7}, {%8,%9}, {%0,%1,%2,%3};"
        : "+f"(d[0]), "+f"(d[1]), "+f"(d[2]), "+f"(d[3])
        : "r"(a0), "r"(a1), "r"(a2), "r"(a3), "r"(b0), "r"(b1));
}
__device__ __forceinline__ void ldsm4(unsigned& r0, unsigned& r1, unsigned& r2, unsigned& r3,
                                      uint32_t addr) {
    asm volatile("ldmatrix.sync.aligned.m8n8.x4.shared.b16 {%0,%1,%2,%3}, [%4];"
                 : "=r"(r0), "=r"(r1), "=r"(r2), "=r"(r3) : "r"(addr));
}
__device__ __forceinline__ unsigned h16pack(float lo_elem, float hi_elem) {
    unsigned short s0 = __half_as_ushort(__float2half_rn(lo_elem));
    unsigned short s1 = __half_as_ushort(__float2half_rn(hi_elem));
    return ((unsigned)s1 << 16) | s0;
}

// ---------------- prep: pack W1/W2 (fp16 hi parts) into fragment order ----------------
extern "C" __global__ void wm_prep(const float* __restrict__ W1, const float* __restrict__ W2) {
    int idx = blockIdx.x * blockDim.x + threadIdx.x;   // 131072 total
    int lane = idx & 31;
    int nt = (idx >> 5) & 3;
    int ks = (idx >> 7) & 31;
    int w = (idx >> 12) & 15;
    int l = idx >> 16;
    int g = lane >> 2, tig = lane & 3;
    int k0 = ks * 16 + tig * 2;
    int n = (w * 4 + nt) * 8 + g;
    const float* W = l ? W2 : W1;
    uint2 o;
    o.x = h16pack(W[(k0 + 0) * 512 + n], W[(k0 + 1) * 512 + n]);
    o.y = h16pack(W[(k0 + 8) * 512 + n], W[(k0 + 9) * 512 + n]);
    g_wt[idx] = o;
}

// Rigid-body derivatives, moments == 0. I-matrices read from smem (register-lean).
__device__ __forceinline__ void derivs(const float x[12], float F0, float F1, float F2,
                                       const float* __restrict__ Im,
                                       const float* __restrict__ Iv, float dx[12]) {
    float V0 = x[3], V1 = x[4], V2 = x[5];
    float w0 = x[9], w1 = x[10], w2 = x[11];
    float sph, cph, sth, cth, sps, cps;
    sincosf(x[6], &sph, &cph);
    sincosf(x[7], &sth, &cth);
    sincosf(x[8], &sps, &cps);
    dx[0] = (cth * cps) * V0 + (sph * sth * cps - cph * sps) * V1 + (cph * sth * cps + sph * sps) * V2;
    dx[1] = (cth * sps) * V0 + (sph * sth * sps + cph * cps) * V1 + (cph * sth * sps - sph * cps) * V2;
    dx[2] = (-sth) * V0 + (sph * cth) * V1 + (cph * cth) * V2;
    dx[3] = F0 / 1.5f - (w1 * V2 - w2 * V1);
    dx[4] = F1 / 1.5f - (w2 * V0 - w0 * V2);
    dx[5] = F2 / 1.5f - (w0 * V1 - w1 * V0);
    float ic = 1.0f / fmaxf(cth, 1e-6f);
    float tth = sth * ic;
    dx[6] = w0 + sph * tth * w1 + cph * tth * w2;
    dx[7] = cph * w1 - sph * w2;
    dx[8] = (sph * ic) * w1 + (cph * ic) * w2;
    float Iw0 = Im[0] * w0 + Im[1] * w1 + Im[2] * w2;
    float Iw1 = Im[3] * w0 + Im[4] * w1 + Im[5] * w2;
    float Iw2 = Im[6] * w0 + Im[7] * w1 + Im[8] * w2;
    float c0 = w1 * Iw2 - w2 * Iw1;
    float c1 = w2 * Iw0 - w0 * Iw2;
    float c2 = w0 * Iw1 - w1 * Iw0;
    dx[9]  = -(Iv[0] * c0 + Iv[1] * c1 + Iv[2] * c2);
    dx[10] = -(Iv[3] * c0 + Iv[4] * c1 + Iv[5] * c2);
    dx[11] = -(Iv[6] * c0 + Iv[7] * c1 + Iv[8] * c2);
}

extern "C" __global__ void __launch_bounds__(NTH)
wm_rollout(const float* __restrict__ x_t, const float* __restrict__ act,
           const float* __restrict__ Imat_g,
           const float* __restrict__ W0, const float* __restrict__ b0v,
           const float* __restrict__ b1v, const float* __restrict__ b2v,
           const float* __restrict__ W3, const float* __restrict__ b3v,
           const int* __restrict__ seqp, float* __restrict__ out, int Bn) {
    extern __shared__ char raw[];
    Smem& S = *reinterpret_cast<Smem*>(raw);
    const int tid = threadIdx.x;
    const int w2 = tid >> 5, lane = tid & 31;    // 32 warps
    const int g = lane >> 2, tig = lane & 3;

    const int T = seqp[0];
    const int steps = T - 1;
    float* outF = out;
    float* outX = out + (size_t)Bn * 6 * steps;

    // ---- stage weights/biases into smem ----
    for (int i = tid; i < 16 * 512; i += NTH) S.W0s[i] = W0[i];
    for (int i = tid; i < 512 * 3; i += NTH) {
        int k = i / 3, c = i - k * 3;
        S.W3s[i] = W3[k * 6 + c];
    }
    for (int i = tid; i < 512; i += NTH) {
        S.b0s[i] = b0v[i];
        S.b1s[i] = b1v[i];
        S.b2s[i] = b2v[i];
    }
    if (tid < 3) S.b3s[tid] = b3v[tid];

    if (tid == 0) {
        float a = Imat_g[0], b = Imat_g[1], c = Imat_g[2];
        float d = Imat_g[3], e = Imat_g[4], f = Imat_g[5];
        float gg = Imat_g[6], h = Imat_g[7], i = Imat_g[8];
        float A = e * i - f * h, Bc = -(d * i - f * gg), C = d * h - e * gg;
        float id = 1.0f / (a * A + b * Bc + c * C);
        S.Iinv[0] = A * id;  S.Iinv[1] = (c * h - b * i) * id;   S.Iinv[2] = (b * f - c * e) * id;
        S.Iinv[3] = Bc * id; S.Iinv[4] = (a * i - c * gg) * id;  S.Iinv[5] = (c * d - a * f) * id;
        S.Iinv[6] = C * id;  S.Iinv[7] = (b * gg - a * h) * id;  S.Iinv[8] = (a * e - b * d) * id;
#pragma unroll
        for (int k = 0; k < 9; k++) S.Im[k] = Imat_g[k];
    }
    if (tid < BT) {
        const int n = tid;
        const size_t bidx = (size_t)blockIdx.x * BT + n;
#pragma unroll
        for (int s = 0; s < 12; s++) {
            float v = x_t[bidx * 12 + s];
            S.x[n][s] = v;
            outX[bidx * 12 * T + (size_t)s * T] = v;
        }
        // build L0 input for t=0
        S.in[0 * BT + n] = S.x[n][0] * 1.2732395447351628f;
        S.in[1 * BT + n] = S.x[n][1] * 0.5f;
        S.in[2 * BT + n] = S.x[n][2] * 1.2732395447351628f;
        S.in[3 * BT + n] = S.x[n][3] * 0.1f;
        S.in[4 * BT + n] = S.x[n][4] * 0.016666666666666666f;
        S.in[5 * BT + n] = S.x[n][5] * 0.016666666666666666f;
#pragma unroll
        for (int s = 6; s < 12; s++) S.in[s * BT + n] = 0.f;
#pragma unroll
        for (int a = 0; a < 4; a++)
            S.in[(12 + a) * BT + n] = (act[(bidx * 4 + a) * T + 1] - 1500.0f) / 500.0f;
    }
    __syncthreads();

    // ldmatrix lane base addresses: row = lane&15, k offset += (lane>>4)*8
    const uint32_t ahBase = s2u(S.Ah) + (uint32_t)(((lane & 15) * AST + ((lane >> 4) << 3)) * 2);
    const uint32_t alBase = ahBase + BT * AST * 2;
    float* h3 = (float*)S.Ah;   // overlay: 16*520 floats == Ah+Al bytes

    for (int t = 0; t < steps; t++) {
        // ---- L0 scalar (weights from smem): neuron c = tid, threads 0..511 ----
        if (tid < 512) {
            const int c = tid;
            ull acc[8];
#pragma unroll
            for (int p = 0; p < 8; p++) acc[p] = 0ULL;
#pragma unroll
            for (int k = 0; k < 16; k++) {
                ull wk = pack2(S.W0s[k * 512 + c]);
                const ull* a = (const ull*)(S.in + k * BT);
#pragma unroll
                for (int p = 0; p < 8; p++) acc[p] = fma2(a[p], wk, acc[p]);
            }
            const float bias = S.b0s[c];
#pragma unroll
            for (int p = 0; p < 8; p++) {
                float2 v = unpack2(acc[p]);
                float h0 = leaky(v.x + bias);
                float h1 = leaky(v.y + bias);
                __half hh0 = __float2half_rn(h0);
                __half hh1 = __float2half_rn(h1);
                S.Ah[(2 * p) * AST + c] = hh0;
                S.Ah[(2 * p + 1) * AST + c] = hh1;
                S.Al[(2 * p) * AST + c] = __float2half_rn(h0 - __half2float(hh0));
                S.Al[(2 * p + 1) * AST + c] = __float2half_rn(h1 - __half2float(hh1));
            }
        }
        __syncthreads();

        // ---- two MMA layers: 32 warps x 2 ntiles ----
#pragma unroll
        for (int la = 0; la < 2; la++) {
            float d0[2][4], d1[2][4];
#pragma unroll
            for (int nt = 0; nt < 2; nt++)
#pragma unroll
                for (int q = 0; q < 4; q++) { d0[nt][q] = 0.f; d1[nt][q] = 0.f; }

            // reuse 16-warp g_wt layout: w_old = w2>>1, nt_old = (w2&1)*2 + nt
            const uint2* wbase = g_wt + ((size_t)la * 65536 + (w2 >> 1) * 4096 + (w2 & 1) * 64 + lane);
            // 4-deep W register ring (prefetch distance ~ L2 latency at 8 warps/SMSP)
            uint2 wreg[4][2];
#pragma unroll
            for (int s = 0; s < 4; s++) {
                wreg[s][0] = wbase[s * 128];
                wreg[s][1] = wbase[s * 128 + 32];
            }

#pragma unroll
            for (int ks = 0; ks < 32; ks++) {
                const int slot = ks & 3;
                unsigned ah0, ah1, ah2, ah3, al0, al1, al2, al3;
                ldsm4(ah0, ah1, ah2, ah3, ahBase + ks * 32);
                ldsm4(al0, al1, al2, al3, alBase + ks * 32);
                // 4 independent chains
                mma16816(d0[0], ah0, ah1, ah2, ah3, wreg[slot][0].x, wreg[slot][0].y);
                mma16816(d0[1], ah0, ah1, ah2, ah3, wreg[slot][1].x, wreg[slot][1].y);
                mma16816(d1[0], al0, al1, al2, al3, wreg[slot][0].x, wreg[slot][0].y);
                mma16816(d1[1], al0, al1, al2, al3, wreg[slot][1].x, wreg[slot][1].y);
                if (ks + 4 < 32) {
                    wreg[slot][0] = wbase[(ks + 4) * 128];
                    wreg[slot][1] = wbase[(ks + 4) * 128 + 32];
                }
            }
            __syncthreads();   // all A reads done before overwrite

            if (la == 0) {
#pragma unroll
                for (int nt = 0; nt < 2; nt++) {
                    const int nb = w2 * 16 + nt * 8 + tig * 2;
                    const float bb0 = S.b1s[nb], bb1 = S.b1s[nb + 1];
                    float h00 = leaky(d0[nt][0] + d1[nt][0] + bb0);
                    float h01 = leaky(d0[nt][1] + d1[nt][1] + bb1);
                    float h10 = leaky(d0[nt][2] + d1[nt][2] + bb0);
                    float h11 = leaky(d0[nt][3] + d1[nt][3] + bb1);
                    __half a00 = __float2half_rn(h00);
                    __half a01 = __float2half_rn(h01);
                    __half a10 = __float2half_rn(h10);
                    __half a11 = __float2half_rn(h11);
                    unsigned* AhW = (unsigned*)S.Ah;
                    unsigned* AlW = (unsigned*)S.Al;
                    AhW[(g * AST + nb) >> 1] =
                        ((unsigned)__half_as_ushort(a01) << 16) | __half_as_ushort(a00);
                    AhW[((g + 8) * AST + nb) >> 1] =
                        ((unsigned)__half_as_ushort(a11) << 16) | __half_as_ushort(a10);
                    AlW[(g * AST + nb) >> 1] =
                        ((unsigned)__half_as_ushort(__float2half_rn(h01 - __half2float(a01))) << 16) |
                        __half_as_ushort(__float2half_rn(h00 - __half2float(a00)));
                    AlW[((g + 8) * AST + nb) >> 1] =
                        ((unsigned)__half_as_ushort(__float2half_rn(h11 - __half2float(a11))) << 16) |
                        __half_as_ushort(__float2half_rn(h10 - __half2float(a10)));
                }
            } else {
#pragma unroll
                for (int nt = 0; nt < 2; nt++) {
                    const int nb = w2 * 16 + nt * 8 + tig * 2;
                    const float bb0 = S.b2s[nb], bb1 = S.b2s[nb + 1];
                    float2 r0, r1;
                    r0.x = leaky(d0[nt][0] + d1[nt][0] + bb0);
                    r0.y = leaky(d0[nt][1] + d1[nt][1] + bb1);
                    r1.x = leaky(d0[nt][2] + d1[nt][2] + bb0);
                    r1.y = leaky(d0[nt][3] + d1[nt][3] + bb1);
                    *(float2*)(h3 + g * AST + nb) = r0;
                    *(float2*)(h3 + (g + 8) * AST + nb) = r1;
                }
            }
            __syncthreads();
        }

        // ---- L3 (weights from smem) + warp shuffle reduce ----
        if (tid < 384) {
            const int o = tid >> 3, q = tid & 7;
            const int n = o / 3, c = o - n * 3;
            const float* hp = h3 + n * AST + q * 64;
            float s0 = 0.f, s1 = 0.f;
            const int kb = q * 64;
#pragma unroll 8
            for (int k = 0; k < 64; k += 2) {
                s0 = fmaf(hp[k], S.W3s[(kb + k) * 3 + c], s0);
                s1 = fmaf(hp[k + 1], S.W3s[(kb + k + 1) * 3 + c], s1);
            }
            float s = s0 + s1;
#pragma unroll
            for (int dsh = 4; dsh >= 1; dsh >>= 1)
                s += __shfl_xor_sync(0xffffffffu, s, dsh);
            if (q == 0) S.fn[n][c] = s + S.b3s[c];
        }
        __syncthreads();

        // ---- forces + RK4 (register-lean) + outputs + next-step input build ----
        if (tid < BT) {
            const int n = tid;
            const size_t bidx = (size_t)blockIdx.x * BT + n;
            const float F0 = S.fn[n][0] - 0.5f;
            const float F1 = S.fn[n][1] * (-0.4f) - 10.0f;
            const float F2 = S.fn[n][2] * 0.2f - 0.1f;
            float* fo = outF + bidx * 6 * steps + t;
            fo[0 * steps] = F0;
            fo[1 * steps] = F1;
            fo[2 * steps] = F2;
            fo[3 * steps] = 0.f;
            fo[4 * steps] = 0.f;
            fo[5 * steps] = 0.f;
            const float w6 = (float)(0.01 / 6.0);
            const float w3 = (float)(0.01 / 3.0);
            float xx[12], tm[12], kk[12], accs[12];
#pragma unroll
            for (int s = 0; s < 12; s++) xx[s] = S.x[n][s];
            derivs(xx, F0, F1, F2, S.Im, S.Iinv, kk);
#pragma unroll
            for (int s = 0; s < 12; s++) { accs[s] = xx[s] + w6 * kk[s]; tm[s] = xx[s] + 0.005f * kk[s]; }
            derivs(tm, F0, F1, F2, S.Im, S.Iinv, kk);
#pragma unroll
            for (int s = 0; s < 12; s++) { accs[s] += w3 * kk[s]; tm[s] = xx[s] + 0.005f * kk[s]; }
            derivs(tm, F0, F1, F2, S.Im, S.Iinv, kk);
#pragma unroll
            for (int s = 0; s < 12; s++) { accs[s] += w3 * kk[s]; tm[s] = xx[s] + 0.01f * kk[s]; }
            derivs(tm, F0, F1, F2, S.Im, S.Iinv, kk);
#pragma unroll
            for (int s = 0; s < 12; s++) accs[s] += w6 * kk[s];

            float* xo = outX + bidx * 12 * T + (t + 1);
#pragma unroll
            for (int s = 0; s < 12; s++) {
                S.x[n][s] = accs[s];
                xo[(size_t)s * T] = accs[s];
            }
            if (t + 1 < steps) {
                S.in[0 * BT + n] = accs[0] * 1.2732395447351628f;
                S.in[1 * BT + n] = accs[1] * 0.5f;
                S.in[2 * BT + n] = accs[2] * 1.2732395447351628f;
                S.in[3 * BT + n] = accs[3] * 0.1f;
                S.in[4 * BT + n] = accs[4] * 0.016666666666666666f;
                S.in[5 * BT + n] = accs[5] * 0.016666666666666666f;
#pragma unroll
                for (int a = 0; a < 4; a++)
                    S.in[(12 + a) * BT + n] = (act[(bidx * 4 + a) * T + (t + 2)] - 1500.0f) / 500.0f;
            }
        }
        __syncthreads();
    }
}

extern "C" void kernel_launch(void* const* d_in, const int* in_sizes, int n_in,
                              void* d_out, int out_size) {
    // 0: x_t, 1: act_inps, 2: I_mat, 3: seq_len, 4..11: W0,b0,W1,b1,W2,b2,W3,b3
    const float* x_t = (const float*)d_in[0];
    const float* act = (const float*)d_in[1];
    const float* Im  = (const float*)d_in[2];
    const int* seqp  = (const int*)d_in[3];
    const float* W0  = (const float*)d_in[4];
    const float* b0  = (const float*)d_in[5];
    const float* W1  = (const float*)d_in[6];
    const float* b1  = (const float*)d_in[7];
    const float* W2  = (const float*)d_in[8];
    const float* b2  = (const float*)d_in[9];
    const float* W3  = (const float*)d_in[10];
    const float* b3  = (const float*)d_in[11];

    const int Bn = in_sizes[0] / 12;
    const int grid = Bn / BT;
    const size_t sm = sizeof(Smem);

    wm_prep<<<256, 512>>>(W1, W2);
    cudaFuncSetAttribute(wm_rollout, cudaFuncAttributeMaxDynamicSharedMemorySize, (int)sm);
    wm_rollout<<<grid, NTH, sm>>>(x_t, act, Im, W0, b0, b1, b2, W3, b3,
                                  seqp, (float*)d_out, Bn);
}

// round 17
// speedup vs baseline: 1.2275x; 1.2275x over previous
#include <cuda_runtime.h>
#include <cuda_fp16.h>
#include <math.h>
#include <stdint.h>

#define NTH 512
#define BT 16
#define HD 512
#define AST 520   // activation row stride in elems (1040B = 65*16B -> ldmatrix-aligned, conflict-free)

typedef unsigned long long ull;

// Fragment-packed fp16 weights (hi parts): uint4 per (layer, warp16, kstep, ntpair, lane)
// uint4 = {nt0.b0, nt0.b1, nt1.b0, nt1.b1}
__device__ __align__(16) uint4 g_wt[2 * 16 * 32 * 2 * 32];

struct Smem {
    __half AhA[BT * AST];  // layer-1 input hi  (h3 fp32 overlays AhA+AlA)
    __half AlA[BT * AST];  // layer-1 input lo
    __half AhB[BT * AST];  // layer-2 input hi
    __half AlB[BT * AST];  // layer-2 input lo
    float W0s[16 * 512];
    float W3s[512 * 3];
    float b0s[512], b1s[512], b2s[512];
    float in[16 * BT];     // L0 input col-major [k][row]
    float x[BT][12];
    float fn[BT][3];
    float Im[9], Iinv[9], b3s[3];
};

__device__ __forceinline__ float leaky(float v) { return v >= 0.f ? v : 0.01f * v; }
__device__ __forceinline__ ull fma2(ull a, ull b, ull c) {
    ull d;
    asm("fma.rn.f32x2 %0, %1, %2, %3;" : "=l"(d) : "l"(a), "l"(b), "l"(c));
    return d;
}
__device__ __forceinline__ ull pack2(float x) {
    ull r;
    asm("mov.b64 %0, {%1, %1};" : "=l"(r) : "f"(x));
    return r;
}
__device__ __forceinline__ float2 unpack2(ull v) {
    float2 f;
    asm("mov.b64 {%0, %1}, %2;" : "=f"(f.x), "=f"(f.y) : "l"(v));
    return f;
}
__device__ __forceinline__ uint32_t s2u(const void* p) {
    uint32_t a;
    asm("{ .reg .u64 t; cvta.to.shared.u64 t, %1; cvt.u32.u64 %0, t; }" : "=r"(a) : "l"(p));
    return a;
}

__device__ __forceinline__ void mma16816(float d[4], unsigned a0, unsigned a1, unsigned a2,
                                         unsigned a3, unsigned b0, unsigned b1) {
    asm volatile(
        "mma.sync.aligned.m16n8k16.row.col.f32.f16.f16.f32 "
        "{%0,%1,%2,%3}, {%4,%5,%6,%7}, {%8,%9}, {%0,%1,%2,%3};"
        : "+f"(d[0]), "+f"(d[1]), "+f"(d[2]), "+f"(d[3])
        : "r"(a0), "r"(a1), "r"(a2), "r"(a3), "r"(b0), "r"(b1));
}
__device__ __forceinline__ void ldsm4(unsigned& r0, unsigned& r1, unsigned& r2, unsigned& r3,
                                      uint32_t addr) {
    asm volatile("ldmatrix.sync.aligned.m8n8.x4.shared.b16 {%0,%1,%2,%3}, [%4];"
                 : "=r"(r0), "=r"(r1), "=r"(r2), "=r"(r3) : "r"(addr));
}
__device__ __forceinline__ unsigned h16pack(float lo_elem, float hi_elem) {
    unsigned short s0 = __half_as_ushort(__float2half_rn(lo_elem));
    unsigned short s1 = __half_as_ushort(__float2half_rn(hi_elem));
    return ((unsigned)s1 << 16) | s0;
}

// ---------------- prep: pack W1/W2 (fp16 hi parts), ntile-paired uint4 ----------------
extern "C" __global__ void wm_prep(const float* __restrict__ W1, const float* __restrict__ W2) {
    int idx = blockIdx.x * blockDim.x + threadIdx.x;   // 65536 total
    int lane = idx & 31;
    int p = (idx >> 5) & 1;
    int ks = (idx >> 6) & 31;
    int w = (idx >> 11) & 15;
    int l = idx >> 15;
    int g = lane >> 2, tig = lane & 3;
    int k0 = ks * 16 + tig * 2;
    const float* W = l ? W2 : W1;
    int n0 = (w * 4 + 2 * p) * 8 + g;
    int n1 = (w * 4 + 2 * p + 1) * 8 + g;
    uint4 o;
    o.x = h16pack(W[(k0 + 0) * 512 + n0], W[(k0 + 1) * 512 + n0]);
    o.y = h16pack(W[(k0 + 8) * 512 + n0], W[(k0 + 9) * 512 + n0]);
    o.z = h16pack(W[(k0 + 0) * 512 + n1], W[(k0 + 1) * 512 + n1]);
    o.w = h16pack(W[(k0 + 8) * 512 + n1], W[(k0 + 9) * 512 + n1]);
    g_wt[idx] = o;
}

// Rigid-body derivatives, moments == 0. sincosf-based.
__device__ __forceinline__ void derivs(const float x[12], float F0, float F1, float F2,
                                       const float* __restrict__ Im,
                                       const float* __restrict__ Iv, float dx[12]) {
    float V0 = x[3], V1 = x[4], V2 = x[5];
    float w0 = x[9], w1 = x[10], w2 = x[11];
    float sph, cph, sth, cth, sps, cps;
    sincosf(x[6], &sph, &cph);
    sincosf(x[7], &sth, &cth);
    sincosf(x[8], &sps, &cps);
    dx[0] = (cth * cps) * V0 + (sph * sth * cps - cph * sps) * V1 + (cph * sth * cps + sph * sps) * V2;
    dx[1] = (cth * sps) * V0 + (sph * sth * sps + cph * cps) * V1 + (cph * sth * sps - sph * cps) * V2;
    dx[2] = (-sth) * V0 + (sph * cth) * V1 + (cph * cth) * V2;
    dx[3] = F0 / 1.5f - (w1 * V2 - w2 * V1);
    dx[4] = F1 / 1.5f - (w2 * V0 - w0 * V2);
    dx[5] = F2 / 1.5f - (w0 * V1 - w1 * V0);
    float ic = 1.0f / fmaxf(cth, 1e-6f);
    float tth = sth * ic;
    dx[6] = w0 + sph * tth * w1 + cph * tth * w2;
    dx[7] = cph * w1 - sph * w2;
    dx[8] = (sph * ic) * w1 + (cph * ic) * w2;
    float Iw0 = Im[0] * w0 + Im[1] * w1 + Im[2] * w2;
    float Iw1 = Im[3] * w0 + Im[4] * w1 + Im[5] * w2;
    float Iw2 = Im[6] * w0 + Im[7] * w1 + Im[8] * w2;
    float c0 = w1 * Iw2 - w2 * Iw1;
    float c1 = w2 * Iw0 - w0 * Iw2;
    float c2 = w0 * Iw1 - w1 * Iw0;
    dx[9]  = -(Iv[0] * c0 + Iv[1] * c1 + Iv[2] * c2);
    dx[10] = -(Iv[3] * c0 + Iv[4] * c1 + Iv[5] * c2);
    dx[11] = -(Iv[6] * c0 + Iv[7] * c1 + Iv[8] * c2);
}

extern "C" __global__ void __launch_bounds__(NTH)
wm_rollout(const float* __restrict__ x_t, const float* __restrict__ act,
           const float* __restrict__ Imat_g,
           const float* __restrict__ W0, const float* __restrict__ b0v,
           const float* __restrict__ b1v, const float* __restrict__ b2v,
           const float* __restrict__ W3, const float* __restrict__ b3v,
           const int* __restrict__ seqp, float* __restrict__ out, int Bn) {
    extern __shared__ char raw[];
    Smem& S = *reinterpret_cast<Smem*>(raw);
    const int tid = threadIdx.x;
    const int w = tid >> 5, lane = tid & 31;
    const int g = lane >> 2, tig = lane & 3;

    const int T = seqp[0];
    const int steps = T - 1;
    float* outF = out;
    float* outX = out + (size_t)Bn * 6 * steps;

    // ---- stage weights/biases into smem ----
    for (int i = tid; i < 16 * 512; i += NTH) S.W0s[i] = W0[i];
    for (int i = tid; i < 512 * 3; i += NTH) {
        int k = i / 3, c = i - k * 3;
        S.W3s[i] = W3[k * 6 + c];
    }
    for (int i = tid; i < 512; i += NTH) {
        S.b0s[i] = b0v[i];
        S.b1s[i] = b1v[i];
        S.b2s[i] = b2v[i];
    }
    if (tid < 3) S.b3s[tid] = b3v[tid];

    if (tid == 0) {
        float a = Imat_g[0], b = Imat_g[1], c = Imat_g[2];
        float d = Imat_g[3], e = Imat_g[4], f = Imat_g[5];
        float gg = Imat_g[6], h = Imat_g[7], i = Imat_g[8];
        float A = e * i - f * h, Bc = -(d * i - f * gg), C = d * h - e * gg;
        float id = 1.0f / (a * A + b * Bc + c * C);
        S.Iinv[0] = A * id;  S.Iinv[1] = (c * h - b * i) * id;   S.Iinv[2] = (b * f - c * e) * id;
        S.Iinv[3] = Bc * id; S.Iinv[4] = (a * i - c * gg) * id;  S.Iinv[5] = (c * d - a * f) * id;
        S.Iinv[6] = C * id;  S.Iinv[7] = (b * gg - a * h) * id;  S.Iinv[8] = (a * e - b * d) * id;
#pragma unroll
        for (int k = 0; k < 9; k++) S.Im[k] = Imat_g[k];
    }
    if (tid < BT) {
        const int n = tid;
        const size_t bidx = (size_t)blockIdx.x * BT + n;
#pragma unroll
        for (int s = 0; s < 12; s++) {
            float v = x_t[bidx * 12 + s];
            S.x[n][s] = v;
            outX[bidx * 12 * T + (size_t)s * T] = v;
        }
        S.in[0 * BT + n] = S.x[n][0] * 1.2732395447351628f;
        S.in[1 * BT + n] = S.x[n][1] * 0.5f;
        S.in[2 * BT + n] = S.x[n][2] * 1.2732395447351628f;
        S.in[3 * BT + n] = S.x[n][3] * 0.1f;
        S.in[4 * BT + n] = S.x[n][4] * 0.016666666666666666f;
        S.in[5 * BT + n] = S.x[n][5] * 0.016666666666666666f;
#pragma unroll
        for (int s = 6; s < 12; s++) S.in[s * BT + n] = 0.f;
#pragma unroll
        for (int a = 0; a < 4; a++)
            S.in[(12 + a) * BT + n] = (act[(bidx * 4 + a) * T + 1] - 1500.0f) / 500.0f;
    }
    __syncthreads();

    // ldmatrix lane base addresses
    const uint32_t laneOff = (uint32_t)(((lane & 15) * AST + ((lane >> 4) << 3)) * 2);
    const uint32_t ahA = s2u(S.AhA) + laneOff;
    const uint32_t alA = s2u(S.AlA) + laneOff;
    const uint32_t ahB = s2u(S.AhB) + laneOff;
    const uint32_t alB = s2u(S.AlB) + laneOff;
    float* h3 = (float*)S.AhA;   // overlay: 16*520 floats == AhA+AlA bytes

    for (int t = 0; t < steps; t++) {
        // ---- L0 scalar (weights from smem): neuron c = tid -> bufA ----
        {
            const int c = tid;
            ull acc[8];
#pragma unroll
            for (int p = 0; p < 8; p++) acc[p] = 0ULL;
#pragma unroll
            for (int k = 0; k < 16; k++) {
                ull wk = pack2(S.W0s[k * 512 + c]);
                const ull* a = (const ull*)(S.in + k * BT);
#pragma unroll
                for (int p = 0; p < 8; p++) acc[p] = fma2(a[p], wk, acc[p]);
            }
            const float bias = S.b0s[c];
#pragma unroll
            for (int p = 0; p < 8; p++) {
                float2 v = unpack2(acc[p]);
                float h0 = leaky(v.x + bias);
                float h1 = leaky(v.y + bias);
                __half hh0 = __float2half_rn(h0);
                __half hh1 = __float2half_rn(h1);
                S.AhA[(2 * p) * AST + c] = hh0;
                S.AhA[(2 * p + 1) * AST + c] = hh1;
                S.AlA[(2 * p) * AST + c] = __float2half_rn(h0 - __half2float(hh0));
                S.AlA[(2 * p + 1) * AST + c] = __float2half_rn(h1 - __half2float(hh1));
            }
        }
        __syncthreads();   // bar1: bufA ready

        // ---- two MMA layers, no barrier between MMA loop and epilogue ----
#pragma unroll
        for (int la = 0; la < 2; la++) {
            const uint32_t ahSrc = la ? ahB : ahA;
            const uint32_t alSrc = la ? alB : alA;
            float d0[4][4], d1[4][4];
#pragma unroll
            for (int nt = 0; nt < 4; nt++)
#pragma unroll
                for (int q = 0; q < 4; q++) { d0[nt][q] = 0.f; d1[nt][q] = 0.f; }

            const uint4* wbase = g_wt + ((size_t)la * 32768 + w * 2048 + lane);
            uint4 wreg[3][2];
#pragma unroll
            for (int s = 0; s < 3; s++) {
                wreg[s][0] = wbase[s * 64];
                wreg[s][1] = wbase[s * 64 + 32];
            }

#pragma unroll
            for (int ks = 0; ks < 32; ks++) {
                const int slot = ks % 3;
                unsigned ah0, ah1, ah2, ah3, al0, al1, al2, al3;
                ldsm4(ah0, ah1, ah2, ah3, ahSrc + ks * 32);
                ldsm4(al0, al1, al2, al3, alSrc + ks * 32);
                // term-major: 8 independent chains
                mma16816(d0[0], ah0, ah1, ah2, ah3, wreg[slot][0].x, wreg[slot][0].y);
                mma16816(d0[1], ah0, ah1, ah2, ah3, wreg[slot][0].z, wreg[slot][0].w);
                mma16816(d0[2], ah0, ah1, ah2, ah3, wreg[slot][1].x, wreg[slot][1].y);
                mma16816(d0[3], ah0, ah1, ah2, ah3, wreg[slot][1].z, wreg[slot][1].w);
                mma16816(d1[0], al0, al1, al2, al3, wreg[slot][0].x, wreg[slot][0].y);
                mma16816(d1[1], al0, al1, al2, al3, wreg[slot][0].z, wreg[slot][0].w);
                mma16816(d1[2], al0, al1, al2, al3, wreg[slot][1].x, wreg[slot][1].y);
                mma16816(d1[3], al0, al1, al2, al3, wreg[slot][1].z, wreg[slot][1].w);
                if (ks + 3 < 32) {
                    wreg[slot][0] = wbase[(ks + 3) * 64];
                    wreg[slot][1] = wbase[(ks + 3) * 64 + 32];
                }
            }
            // epilogue (warp-local accumulators; writes the OTHER buffer -> no bar needed)
            if (la == 0) {
#pragma unroll
                for (int nt = 0; nt < 4; nt++) {
                    const int nb = w * 32 + nt * 8 + tig * 2;
                    const float bb0 = S.b1s[nb], bb1 = S.b1s[nb + 1];
                    float h00 = leaky(d0[nt][0] + d1[nt][0] + bb0);
                    float h01 = leaky(d0[nt][1] + d1[nt][1] + bb1);
                    float h10 = leaky(d0[nt][2] + d1[nt][2] + bb0);
                    float h11 = leaky(d0[nt][3] + d1[nt][3] + bb1);
                    __half a00 = __float2half_rn(h00);
                    __half a01 = __float2half_rn(h01);
                    __half a10 = __float2half_rn(h10);
                    __half a11 = __float2half_rn(h11);
                    unsigned* AhW = (unsigned*)S.AhB;
                    unsigned* AlW = (unsigned*)S.AlB;
                    AhW[(g * AST + nb) >> 1] =
                        ((unsigned)__half_as_ushort(a01) << 16) | __half_as_ushort(a00);
                    AhW[((g + 8) * AST + nb) >> 1] =
                        ((unsigned)__half_as_ushort(a11) << 16) | __half_as_ushort(a10);
                    AlW[(g * AST + nb) >> 1] =
                        ((unsigned)__half_as_ushort(__float2half_rn(h01 - __half2float(a01))) << 16) |
                        __half_as_ushort(__float2half_rn(h00 - __half2float(a00)));
                    AlW[((g + 8) * AST + nb) >> 1] =
                        ((unsigned)__half_as_ushort(__float2half_rn(h11 - __half2float(a11))) << 16) |
                        __half_as_ushort(__float2half_rn(h10 - __half2float(a10)));
                }
            } else {
#pragma unroll
                for (int nt = 0; nt < 4; nt++) {
                    const int nb = w * 32 + nt * 8 + tig * 2;
                    const float bb0 = S.b2s[nb], bb1 = S.b2s[nb + 1];
                    float2 r0, r1;
                    r0.x = leaky(d0[nt][0] + d1[nt][0] + bb0);
                    r0.y = leaky(d0[nt][1] + d1[nt][1] + bb1);
                    r1.x = leaky(d0[nt][2] + d1[nt][2] + bb0);
                    r1.y = leaky(d0[nt][3] + d1[nt][3] + bb1);
                    *(float2*)(h3 + g * AST + nb) = r0;        // h3 overlays bufA (disjoint from bufB reads)
                    *(float2*)(h3 + (g + 8) * AST + nb) = r1;
                }
            }
            __syncthreads();   // bar2 / bar3: next stage's operand buffer ready
        }

        // ---- L3 (weights from smem) + warp shuffle reduce ----
        if (tid < 384) {
            const int o = tid >> 3, q = tid & 7;
            const int n = o / 3, c = o - n * 3;
            const float* hp = h3 + n * AST + q * 64;
            float s0 = 0.f, s1 = 0.f;
            const int kb = q * 64;
#pragma unroll 8
            for (int k = 0; k < 64; k += 2) {
                s0 = fmaf(hp[k], S.W3s[(kb + k) * 3 + c], s0);
                s1 = fmaf(hp[k + 1], S.W3s[(kb + k + 1) * 3 + c], s1);
            }
            float s = s0 + s1;
#pragma unroll
            for (int dsh = 4; dsh >= 1; dsh >>= 1)
                s += __shfl_xor_sync(0xffffffffu, s, dsh);
            if (q == 0) S.fn[n][c] = s + S.b3s[c];
        }
        __syncthreads();   // bar4: fn ready

        // ---- forces + RK4 + outputs + next-step input build ----
        if (tid < BT) {
            const int n = tid;
            const size_t bidx = (size_t)blockIdx.x * BT + n;
            const float F0 = S.fn[n][0] - 0.5f;
            const float F1 = S.fn[n][1] * (-0.4f) - 10.0f;
            const float F2 = S.fn[n][2] * 0.2f - 0.1f;
            float* fo = outF + bidx * 6 * steps + t;
            fo[0 * steps] = F0;
            fo[1 * steps] = F1;
            fo[2 * steps] = F2;
            fo[3 * steps] = 0.f;
            fo[4 * steps] = 0.f;
            fo[5 * steps] = 0.f;
            const float w6 = (float)(0.01 / 6.0);
            const float w3 = (float)(0.01 / 3.0);
            float xx[12], tm[12], kk[12], accs[12];
#pragma unroll
            for (int s = 0; s < 12; s++) xx[s] = S.x[n][s];
            derivs(xx, F0, F1, F2, S.Im, S.Iinv, kk);
#pragma unroll
            for (int s = 0; s < 12; s++) { accs[s] = xx[s] + w6 * kk[s]; tm[s] = xx[s] + 0.005f * kk[s]; }
            derivs(tm, F0, F1, F2, S.Im, S.Iinv, kk);
#pragma unroll
            for (int s = 0; s < 12; s++) { accs[s] += w3 * kk[s]; tm[s] = xx[s] + 0.005f * kk[s]; }
            derivs(tm, F0, F1, F2, S.Im, S.Iinv, kk);
#pragma unroll
            for (int s = 0; s < 12; s++) { accs[s] += w3 * kk[s]; tm[s] = xx[s] + 0.01f * kk[s]; }
            derivs(tm, F0, F1, F2, S.Im, S.Iinv, kk);
#pragma unroll
            for (int s = 0; s < 12; s++) accs[s] += w6 * kk[s];

            float* xo = outX + bidx * 12 * T + (t + 1);
#pragma unroll
            for (int s = 0; s < 12; s++) {
                S.x[n][s] = accs[s];
                xo[(size_t)s * T] = accs[s];
            }
            if (t + 1 < steps) {
                S.in[0 * BT + n] = accs[0] * 1.2732395447351628f;
                S.in[1 * BT + n] = accs[1] * 0.5f;
                S.in[2 * BT + n] = accs[2] * 1.2732395447351628f;
                S.in[3 * BT + n] = accs[3] * 0.1f;
                S.in[4 * BT + n] = accs[4] * 0.016666666666666666f;
                S.in[5 * BT + n] = accs[5] * 0.016666666666666666f;
#pragma unroll
                for (int a = 0; a < 4; a++)
                    S.in[(12 + a) * BT + n] = (act[(bidx * 4 + a) * T + (t + 2)] - 1500.0f) / 500.0f;
            }
        }
        __syncthreads();   // bar5: state/input ready for next step
    }
}

extern "C" void kernel_launch(void* const* d_in, const int* in_sizes, int n_in,
                              void* d_out, int out_size) {
    // 0: x_t, 1: act_inps, 2: I_mat, 3: seq_len, 4..11: W0,b0,W1,b1,W2,b2,W3,b3
    const float* x_t = (const float*)d_in[0];
    const float* act = (const float*)d_in[1];
    const float* Im  = (const float*)d_in[2];
    const int* seqp  = (const int*)d_in[3];
    const float* W0  = (const float*)d_in[4];
    const float* b0  = (const float*)d_in[5];
    const float* W1  = (const float*)d_in[6];
    const float* b1  = (const float*)d_in[7];
    const float* W2  = (const float*)d_in[8];
    const float* b2  = (const float*)d_in[9];
    const float* W3  = (const float*)d_in[10];
    const float* b3  = (const float*)d_in[11];

    const int Bn = in_sizes[0] / 12;
    const int grid = Bn / BT;
    const size_t sm = sizeof(Smem);

    wm_prep<<<128, 512>>>(W1, W2);
    cudaFuncSetAttribute(wm_rollout, cudaFuncAttributeMaxDynamicSharedMemorySize, (int)sm);
    wm_rollout<<<grid, NTH, sm>>>(x_t, act, Im, W0, b0, b1, b2, W3, b3,
                                  seqp, (float*)d_out, Bn);
}